// round 16
// baseline (speedup 1.0000x reference)
#include <cuda_runtime.h>
#include <cuda_bf16.h>
#include <cstdint>

// ---------------- problem constants ----------------
#define NN      50000
#define EE      800000
#define IN_DIM  768
#define HID     256
#define OUT_DIM 128
#define BN_EPS  1e-5f
#define NORM_EPS 1e-12f
#define NBLK    ((NN + 255) / 256)
#define MBLOCKS ((NN + 127) / 128)      // 391
#define CHUNK_BLOCKS 196                 // chunk0 rows = 25088
#define CHUNK_ROWS  (CHUNK_BLOCKS * 128)

// ---------------- scratch (device globals — allocation-free) ----------------
__device__ float g_deg[NN];               // weighted degree -> dis (rsqrt) in place
__device__ float g_t1[(size_t)NN * HID];  // GEMM output buffer A
__device__ float g_t2[(size_t)NN * HID];  // GEMM output buffer B (double-buffer)
__device__ float g_h[(size_t)NN * HID];   // layer input (post BN+ReLU)
__device__ int   g_cnt[NN];               // in-degree count
__device__ int   g_off[NN + 1];           // CSR offsets
__device__ int   g_cursor[NN];            // placement cursors
__device__ int   g_part[NBLK];            // per-block partial sums
__device__ int   g_csr_src[EE];           // src node per CSR slot
__device__ float g_csr_nrm[EE];           // edge norm per CSR slot

// ---------------- helpers ----------------
__device__ __forceinline__ uint32_t smem_u32(const void* p) {
    uint32_t a;
    asm("{ .reg .u64 t; cvta.to.shared.u64 t, %1; cvt.u32.u64 %0, t; }"
        : "=r"(a) : "l"(p));
    return a;
}

__device__ __forceinline__ void cp_async16(uint32_t smem, const void* g) {
    asm volatile("cp.async.cg.shared.global [%0], [%1], 16;"
                 :: "r"(smem), "l"(g) : "memory");
}
#define CP_COMMIT() asm volatile("cp.async.commit_group;" ::: "memory")
#define CP_WAIT0()  asm volatile("cp.async.wait_group 0;" ::: "memory")

// ---- packed f32x2 ----
__device__ __forceinline__ unsigned long long pack2(float v) {
    unsigned long long d;
    asm("mov.b64 %0, {%1, %1};" : "=l"(d) : "f"(v));
    return d;
}
__device__ __forceinline__ void unpack2(unsigned long long v, float& lo, float& hi) {
    asm("mov.b64 {%0, %1}, %2;" : "=f"(lo), "=f"(hi) : "l"(v));
}
__device__ __forceinline__ void ffma2(unsigned long long& c,
                                      unsigned long long a, unsigned long long b) {
    asm("fma.rn.f32x2 %0, %1, %2, %0;" : "+l"(c) : "l"(a), "l"(b));
}

// ---------------- degree / count ----------------
__global__ void k_init(float* deg, int* cnt, int n) {
    int i = blockIdx.x * blockDim.x + threadIdx.x;
    if (i < n) { deg[i] = 1.0f; cnt[i] = 0; }   // self-loop weight 1
}

__global__ void k_deg_cnt(const int* __restrict__ ei, const float* __restrict__ ew,
                          float* deg, int* cnt, int e) {
    int i = blockIdx.x * blockDim.x + threadIdx.x;
    if (i < e) {
        int d = ei[e + i];
        atomicAdd(&deg[d], ew[i]);
        atomicAdd(&cnt[d], 1);
    }
}

__global__ void k_rsqrt(float* deg, int n) {
    int i = blockIdx.x * blockDim.x + threadIdx.x;
    if (i < n) { float d = deg[i]; deg[i] = (d > 0.0f) ? rsqrtf(d) : 0.0f; }
}

// ---------------- multi-block exclusive scan: cnt -> off, cursor ----------------
__device__ __forceinline__ int warp_incl_scan(int v, int lane) {
#pragma unroll
    for (int o = 1; o < 32; o <<= 1) {
        int t = __shfl_up_sync(0xFFFFFFFFu, v, o);
        if (lane >= o) v += t;
    }
    return v;
}

__device__ __forceinline__ int block_incl_scan(int v, int tid) {
    __shared__ int ws[8];
    const int lane = tid & 31, w = tid >> 5;
    int s = warp_incl_scan(v, lane);
    if (lane == 31) ws[w] = s;
    __syncthreads();
    if (w == 0) {
        int t = (lane < 8) ? ws[lane] : 0;
        t = warp_incl_scan(t, lane);
        if (lane < 8) ws[lane] = t;
    }
    __syncthreads();
    return s + ((w > 0) ? ws[w - 1] : 0);
}

__global__ void k_scan_part(const int* __restrict__ cnt, int* __restrict__ part, int n) {
    __shared__ int ws[8];
    int i = blockIdx.x * 256 + threadIdx.x;
    int v = (i < n) ? cnt[i] : 0;
    const int lane = threadIdx.x & 31, w = threadIdx.x >> 5;
#pragma unroll
    for (int o = 16; o > 0; o >>= 1) v += __shfl_xor_sync(0xFFFFFFFFu, v, o);
    if (lane == 0) ws[w] = v;
    __syncthreads();
    if (threadIdx.x == 0) {
        int s = 0;
#pragma unroll
        for (int j = 0; j < 8; j++) s += ws[j];
        part[blockIdx.x] = s;
    }
}

__global__ void k_scan_mid(int* __restrict__ part, int nb) {
    int t = threadIdx.x;
    int v = (t < nb) ? part[t] : 0;
    int incl = block_incl_scan(v, t);
    if (t < nb) part[t] = incl - v;     // exclusive
}

__global__ void k_scan_fin(const int* __restrict__ cnt, const int* __restrict__ part,
                           int* __restrict__ off, int* __restrict__ cursor, int n) {
    int i = blockIdx.x * 256 + threadIdx.x;
    int v = (i < n) ? cnt[i] : 0;
    int incl = block_incl_scan(v, threadIdx.x);
    int excl = part[blockIdx.x] + incl - v;
    if (i < n) { off[i] = excl; cursor[i] = excl; }
    if (i == n - 1) off[n] = excl + v;
}

// ---------------- CSR placement + norm precompute ----------------
__global__ void k_place(const int* __restrict__ ei, const float* __restrict__ ew,
                        const float* __restrict__ dis,
                        int* __restrict__ cursor,
                        int* __restrict__ csrc, float* __restrict__ cnrm, int e) {
    int i = blockIdx.x * blockDim.x + threadIdx.x;
    if (i >= e) return;
    int s = ei[i];
    int d = ei[e + i];
    float nrm = dis[s] * ew[i] * dis[d];
    int pos = atomicAdd(&cursor[d], 1);
    csrc[pos] = s;
    cnrm[pos] = nrm;
}

// ---------------- SGEMM (FFMA2, A prefetch depth 2, row-chunked) ----------------
// BM=128, BN=128, BK=16, 256 threads, 8x8/thread, 2-stage smem pipeline.
__device__ __forceinline__ void tile_mac(const float (*__restrict__ As)[128],
                                         const float (*__restrict__ Bs)[128],
                                         unsigned long long acc2[8][4],
                                         int ty, int tx) {
#pragma unroll
    for (int kk = 0; kk < 16; kk++) {
        float4 fa0 = *(const float4*)&As[kk][ty * 8];
        float4 fa1 = *(const float4*)&As[kk][ty * 8 + 4];
        ulonglong2 fb0 = *(const ulonglong2*)&Bs[kk][tx * 8];
        ulonglong2 fb1 = *(const ulonglong2*)&Bs[kk][tx * 8 + 4];
        unsigned long long b2[4] = {fb0.x, fb0.y, fb1.x, fb1.y};
        unsigned long long a2[8] = {
            pack2(fa0.x), pack2(fa0.y), pack2(fa0.z), pack2(fa0.w),
            pack2(fa1.x), pack2(fa1.y), pack2(fa1.z), pack2(fa1.w)};
#pragma unroll
        for (int i = 0; i < 8; i++)
#pragma unroll
            for (int j = 0; j < 4; j++)
                ffma2(acc2[i][j], a2[i], b2[j]);
    }
}

__global__ __launch_bounds__(256, 2)
void k_sgemm(const float* __restrict__ A, const float* __restrict__ B,
             float* __restrict__ C, int M, int N, int K, int rowBlockOff) {
    __shared__ float As[2][16][128];
    __shared__ float Bs[2][16][128];

    const int tid = threadIdx.x;
    const int tx  = tid & 15;
    const int ty  = tid >> 4;
    const int blockRow = blockIdx.y + rowBlockOff;
    const int blockCol = blockIdx.x;

    const int aRow = tid >> 2;
    const int aCol = (tid & 3) * 4;
    const int bRow = tid >> 5;
    const int bCol = (tid & 31) * 4;

    const float* Ablk = A + (size_t)blockRow * 128 * K;
    const float* Bblk = B + blockCol * 128;

    unsigned long long acc2[8][4];
#pragma unroll
    for (int i = 0; i < 8; i++)
#pragma unroll
        for (int j = 0; j < 4; j++) acc2[i][j] = 0ull;

    float4 ra[2], rb[2];

    // ---- prologue: tile 0 -> smem buf 0; prefetch tile 1 into ra ----
#pragma unroll
    for (int r = 0; r < 2; r++) {
        int row  = aRow + r * 64;
        int grow = blockRow * 128 + row;
        ra[r] = make_float4(0.f, 0.f, 0.f, 0.f);
        if (grow < M)
            ra[r] = *(const float4*)(Ablk + (size_t)row * K + aCol);
    }
#pragma unroll
    for (int r = 0; r < 2; r++) {
        int row = bRow + r * 8;
        cp_async16(smem_u32(&Bs[0][row][bCol]), Bblk + (size_t)row * N + bCol);
    }
    CP_COMMIT();
#pragma unroll
    for (int r = 0; r < 2; r++) {
        int row = aRow + r * 64;
        As[0][aCol + 0][row] = ra[r].x;
        As[0][aCol + 1][row] = ra[r].y;
        As[0][aCol + 2][row] = ra[r].z;
        As[0][aCol + 3][row] = ra[r].w;
    }
    if (K > 16) {
#pragma unroll
        for (int r = 0; r < 2; r++) {
            int row  = aRow + r * 64;
            int grow = blockRow * 128 + row;
            ra[r] = make_float4(0.f, 0.f, 0.f, 0.f);
            if (grow < M)
                ra[r] = *(const float4*)(Ablk + (size_t)row * K + 16 + aCol);
        }
    }
    CP_WAIT0();
    __syncthreads();

    int buf = 0;
    for (int k0 = 16; k0 < K; k0 += 16) {
        int nbuf = buf ^ 1;
#pragma unroll
        for (int r = 0; r < 2; r++) {
            int row = bRow + r * 8;
            cp_async16(smem_u32(&Bs[nbuf][row][bCol]),
                       Bblk + (size_t)(k0 + row) * N + bCol);
        }
        CP_COMMIT();
        const bool have_next = (k0 + 16) < K;
#pragma unroll
        for (int r = 0; r < 2; r++) {
            int row  = aRow + r * 64;
            int grow = blockRow * 128 + row;
            rb[r] = make_float4(0.f, 0.f, 0.f, 0.f);
            if (have_next && grow < M)
                rb[r] = *(const float4*)(Ablk + (size_t)row * K + k0 + 16 + aCol);
        }

        tile_mac(As[buf], Bs[buf], acc2, ty, tx);

#pragma unroll
        for (int r = 0; r < 2; r++) {
            int row = aRow + r * 64;
            As[nbuf][aCol + 0][row] = ra[r].x;
            As[nbuf][aCol + 1][row] = ra[r].y;
            As[nbuf][aCol + 2][row] = ra[r].z;
            As[nbuf][aCol + 3][row] = ra[r].w;
        }
        ra[0] = rb[0]; ra[1] = rb[1];
        CP_WAIT0();
        __syncthreads();
        buf = nbuf;
    }

    tile_mac(As[buf], Bs[buf], acc2, ty, tx);

    int colBase = blockCol * 128 + tx * 8;
#pragma unroll
    for (int i = 0; i < 8; i++) {
        int grow = blockRow * 128 + ty * 8 + i;
        if (grow >= M) continue;
        size_t off = (size_t)grow * N + colBase;
        float4 c0, c1;
        unpack2(acc2[i][0], c0.x, c0.y);
        unpack2(acc2[i][1], c0.z, c0.w);
        unpack2(acc2[i][2], c1.x, c1.y);
        unpack2(acc2[i][3], c1.z, c1.w);
        *(float4*)(C + off)     = c0;
        *(float4*)(C + off + 4) = c1;
    }
}

// ---------------- fused CSR aggregation + BN/ReLU or L2norm (row-chunked) ----------------
template <int F, bool FINAL>
__global__ __launch_bounds__(256)
void k_agg(const float* __restrict__ t,
           const int* __restrict__ off, const int* __restrict__ csrc,
           const float* __restrict__ cnrm,
           const float* __restrict__ bias, const float* __restrict__ dis,
           const float* __restrict__ bg, const float* __restrict__ bb,
           const float* __restrict__ bm, const float* __restrict__ bv,
           float* __restrict__ out, int rowStart, int rowEnd) {
    const int row = rowStart + blockIdx.x * 8 + (threadIdx.x >> 5);
    if (row >= rowEnd) return;
    const int lane = threadIdx.x & 31;
    constexpr int V = F / 128;

    float4 acc[V];
    {
        const float dvv = dis[row];
        const float d2 = dvv * dvv;
        const float4* trow = (const float4*)(t + (size_t)row * F);
#pragma unroll
        for (int j = 0; j < V; j++) {
            float4 tv = trow[lane + j * 32];
            float4 bvv = ((const float4*)bias)[lane + j * 32];
            acc[j].x = bvv.x + tv.x * d2;
            acc[j].y = bvv.y + tv.y * d2;
            acc[j].z = bvv.z + tv.z * d2;
            acc[j].w = bvv.w + tv.w * d2;
        }
    }

    int e = __ldg(&off[row]);
    const int e1 = __ldg(&off[row + 1]);
    for (; e + 1 < e1; e += 2) {
        int s0 = __ldg(&csrc[e]);
        int s1 = __ldg(&csrc[e + 1]);
        float w0 = __ldg(&cnrm[e]);
        float w1 = __ldg(&cnrm[e + 1]);
        const float4* r0 = (const float4*)(t + (size_t)s0 * F);
        const float4* r1 = (const float4*)(t + (size_t)s1 * F);
#pragma unroll
        for (int j = 0; j < V; j++) {
            float4 x0 = r0[lane + j * 32];
            float4 x1 = r1[lane + j * 32];
            acc[j].x += w0 * x0.x + w1 * x1.x;
            acc[j].y += w0 * x0.y + w1 * x1.y;
            acc[j].z += w0 * x0.z + w1 * x1.z;
            acc[j].w += w0 * x0.w + w1 * x1.w;
        }
    }
    if (e < e1) {
        int s0 = __ldg(&csrc[e]);
        float w0 = __ldg(&cnrm[e]);
        const float4* r0 = (const float4*)(t + (size_t)s0 * F);
#pragma unroll
        for (int j = 0; j < V; j++) {
            float4 x0 = r0[lane + j * 32];
            acc[j].x += w0 * x0.x;
            acc[j].y += w0 * x0.y;
            acc[j].z += w0 * x0.z;
            acc[j].w += w0 * x0.w;
        }
    }

    if (FINAL) {
        float ss = acc[0].x * acc[0].x + acc[0].y * acc[0].y
                 + acc[0].z * acc[0].z + acc[0].w * acc[0].w;
#pragma unroll
        for (int o = 16; o > 0; o >>= 1)
            ss += __shfl_xor_sync(0xFFFFFFFFu, ss, o);
        float inv = 1.0f / fmaxf(sqrtf(ss), NORM_EPS);
        float4 o4 = make_float4(acc[0].x * inv, acc[0].y * inv,
                                acc[0].z * inv, acc[0].w * inv);
        ((float4*)(out + (size_t)row * F))[lane] = o4;
    } else {
        float4* orow = (float4*)(out + (size_t)row * F);
#pragma unroll
        for (int j = 0; j < V; j++) {
            int c = lane + j * 32;
            float4 g = ((const float4*)bg)[c];
            float4 b = ((const float4*)bb)[c];
            float4 m = ((const float4*)bm)[c];
            float4 v = ((const float4*)bv)[c];
            float4 o;
            o.x = fmaxf((acc[j].x - m.x) * rsqrtf(v.x + BN_EPS) * g.x + b.x, 0.0f);
            o.y = fmaxf((acc[j].y - m.y) * rsqrtf(v.y + BN_EPS) * g.y + b.y, 0.0f);
            o.z = fmaxf((acc[j].z - m.z) * rsqrtf(v.z + BN_EPS) * g.z + b.z, 0.0f);
            o.w = fmaxf((acc[j].w - m.w) * rsqrtf(v.w + BN_EPS) * g.w + b.w, 0.0f);
            orow[c] = o;
        }
    }
}

// ---------------- launch ----------------
extern "C" void kernel_launch(void* const* d_in, const int* in_sizes, int n_in,
                              void* d_out, int out_size) {
    const float* x   = (const float*)d_in[0];
    const int*   ei  = (const int*)d_in[1];     // int32 (JAX x64 disabled)
    const float* ew  = (const float*)d_in[2];
    const float* W1  = (const float*)d_in[3];
    const float* b1  = (const float*)d_in[4];
    const float* W2  = (const float*)d_in[5];
    const float* b2  = (const float*)d_in[6];
    const float* W3  = (const float*)d_in[7];
    const float* b3  = (const float*)d_in[8];
    const float* bn1_g = (const float*)d_in[9];
    const float* bn1_b = (const float*)d_in[10];
    const float* bn1_m = (const float*)d_in[11];
    const float* bn1_v = (const float*)d_in[12];
    const float* bn2_g = (const float*)d_in[13];
    const float* bn2_b = (const float*)d_in[14];
    const float* bn2_m = (const float*)d_in[15];
    const float* bn2_v = (const float*)d_in[16];
    float* out = (float*)d_out;

    const int n = NN;
    const int e = in_sizes[2];   // 800000

    float *deg, *t1, *t2, *h, *cnrm;
    int *cnt, *off, *cursor, *csrc, *part;
    cudaGetSymbolAddress((void**)&deg, g_deg);
    cudaGetSymbolAddress((void**)&t1,  g_t1);
    cudaGetSymbolAddress((void**)&t2,  g_t2);
    cudaGetSymbolAddress((void**)&h,   g_h);
    cudaGetSymbolAddress((void**)&cnt, g_cnt);
    cudaGetSymbolAddress((void**)&off, g_off);
    cudaGetSymbolAddress((void**)&cursor, g_cursor);
    cudaGetSymbolAddress((void**)&csrc, g_csr_src);
    cudaGetSymbolAddress((void**)&cnrm, g_csr_nrm);
    cudaGetSymbolAddress((void**)&part, g_part);

    static cudaStream_t s_pre = nullptr, s_b = nullptr;
    static cudaEvent_t ev_fork = nullptr, ev_join = nullptr;
    static cudaEvent_t e_a0, e_a1, e_b0, e_b1;
    if (!s_pre) {
        cudaStreamCreateWithFlags(&s_pre, cudaStreamNonBlocking);
        cudaStreamCreateWithFlags(&s_b, cudaStreamNonBlocking);
        cudaEventCreateWithFlags(&ev_fork, cudaEventDisableTiming);
        cudaEventCreateWithFlags(&ev_join, cudaEventDisableTiming);
        cudaEventCreateWithFlags(&e_a0, cudaEventDisableTiming);
        cudaEventCreateWithFlags(&e_a1, cudaEventDisableTiming);
        cudaEventCreateWithFlags(&e_b0, cudaEventDisableTiming);
        cudaEventCreateWithFlags(&e_b1, cudaEventDisableTiming);
    }

    const int TB = 256;
    const int nb = NBLK;
    const int blk0 = CHUNK_BLOCKS;              // 196 row-blocks (25088 rows)
    const int blk1 = MBLOCKS - CHUNK_BLOCKS;    // 195 row-blocks
    const int r0end = CHUNK_ROWS;               // 25088
    const int ab0 = (r0end + 7) / 8;
    const int ab1 = (n - r0end + 7) / 8;

    // ---- fork: graph preprocessing on side stream, layer-1 GEMM on main ----
    cudaEventRecord(ev_fork, 0);
    cudaStreamWaitEvent(s_pre, ev_fork, 0);
    k_init<<<(n + TB - 1) / TB, TB, 0, s_pre>>>(deg, cnt, n);
    k_deg_cnt<<<(e + TB - 1) / TB, TB, 0, s_pre>>>(ei, ew, deg, cnt, e);
    k_rsqrt<<<(n + TB - 1) / TB, TB, 0, s_pre>>>(deg, n);
    k_scan_part<<<nb, 256, 0, s_pre>>>(cnt, part, n);
    k_scan_mid<<<1, 256, 0, s_pre>>>(part, nb);
    k_scan_fin<<<nb, 256, 0, s_pre>>>(cnt, part, off, cursor, n);
    k_place<<<(e + TB - 1) / TB, TB, 0, s_pre>>>(ei, ew, deg, cursor, csrc, cnrm, e);
    cudaEventRecord(ev_join, s_pre);

    // ---- layer 1: GEMM1 (full) on S0 ----
    k_sgemm<<<dim3(HID / 128, MBLOCKS), 256>>>(x, W1, t1, n, HID, IN_DIM, 0);
    cudaStreamWaitEvent(0, ev_join, 0);   // CSR ready before aggregation

    // ---- agg1 chunked on S0; GEMM2 chunked on S1 overlapping ----
    k_agg<HID, false><<<ab0, 256>>>(t1, off, csrc, cnrm, b1, deg,
                                    bn1_g, bn1_b, bn1_m, bn1_v, h, 0, r0end);
    cudaEventRecord(e_a0, 0);
    k_agg<HID, false><<<ab1, 256>>>(t1, off, csrc, cnrm, b1, deg,
                                    bn1_g, bn1_b, bn1_m, bn1_v, h, r0end, n);
    cudaEventRecord(e_a1, 0);

    cudaStreamWaitEvent(s_b, e_a0, 0);
    k_sgemm<<<dim3(HID / 128, blk0), 256, 0, s_b>>>(h, W2, t2, n, HID, HID, 0);
    cudaStreamWaitEvent(s_b, e_a1, 0);
    k_sgemm<<<dim3(HID / 128, blk1), 256, 0, s_b>>>(h, W2, t2, n, HID, HID, blk0);

    // ---- agg2 chunked on S1; GEMM3 chunked on S0 overlapping ----
    k_agg<HID, false><<<ab0, 256, 0, s_b>>>(t2, off, csrc, cnrm, b2, deg,
                                            bn2_g, bn2_b, bn2_m, bn2_v, h, 0, r0end);
    cudaEventRecord(e_b0, s_b);
    k_agg<HID, false><<<ab1, 256, 0, s_b>>>(t2, off, csrc, cnrm, b2, deg,
                                            bn2_g, bn2_b, bn2_m, bn2_v, h, r0end, n);
    cudaEventRecord(e_b1, s_b);

    cudaStreamWaitEvent(0, e_b0, 0);
    k_sgemm<<<dim3(OUT_DIM / 128, blk0), 256>>>(h, W3, t1, n, OUT_DIM, HID, 0);
    cudaStreamWaitEvent(0, e_b1, 0);
    k_sgemm<<<dim3(OUT_DIM / 128, blk1), 256>>>(h, W3, t1, n, OUT_DIM, HID, blk0);

    // ---- agg3 + l2norm (full) on S0 (joins S1 via e_b0/e_b1 waits above) ----
    k_agg<OUT_DIM, true><<<(n + 7) / 8, 256>>>(t1, off, csrc, cnrm, b3, deg,
                                               nullptr, nullptr, nullptr, nullptr,
                                               out, 0, n);
}

// round 17
// speedup vs baseline: 1.6570x; 1.6570x over previous
#include <cuda_runtime.h>
#include <cuda_bf16.h>
#include <cstdint>

// ---------------- problem constants ----------------
#define NN      50000
#define EE      800000
#define IN_DIM  768
#define HID     256
#define OUT_DIM 128
#define BN_EPS  1e-5f
#define NORM_EPS 1e-12f
#define NBLK    ((NN + 255) / 256)

// ---------------- scratch (device globals — allocation-free) ----------------
__device__ float g_deg[NN];               // weighted degree -> dis (rsqrt) in place
__device__ float g_t[(size_t)NN * HID];   // GEMM output (gather source)
__device__ float g_h[(size_t)NN * HID];   // layer input (post BN+ReLU)
__device__ int   g_cnt[NN];               // in-degree count
__device__ int   g_off[NN + 1];           // CSR offsets
__device__ int   g_cursor[NN];            // placement cursors
__device__ int   g_part[NBLK];            // per-block partial sums
__device__ int   g_csr_src[EE];           // src node per CSR slot
__device__ float g_csr_nrm[EE];           // edge norm per CSR slot

// ---------------- helpers ----------------
__device__ __forceinline__ uint32_t smem_u32(const void* p) {
    uint32_t a;
    asm("{ .reg .u64 t; cvta.to.shared.u64 t, %1; cvt.u32.u64 %0, t; }"
        : "=r"(a) : "l"(p));
    return a;
}

__device__ __forceinline__ void cp_async16(uint32_t smem, const void* g) {
    asm volatile("cp.async.cg.shared.global [%0], [%1], 16;"
                 :: "r"(smem), "l"(g) : "memory");
}
#define CP_COMMIT() asm volatile("cp.async.commit_group;" ::: "memory")
#define CP_WAIT0()  asm volatile("cp.async.wait_group 0;" ::: "memory")

// ---- packed f32x2 ----
__device__ __forceinline__ unsigned long long pack2(float v) {
    unsigned long long d;
    asm("mov.b64 %0, {%1, %1};" : "=l"(d) : "f"(v));
    return d;
}
__device__ __forceinline__ void unpack2(unsigned long long v, float& lo, float& hi) {
    asm("mov.b64 {%0, %1}, %2;" : "=f"(lo), "=f"(hi) : "l"(v));
}
__device__ __forceinline__ void ffma2(unsigned long long& c,
                                      unsigned long long a, unsigned long long b) {
    asm("fma.rn.f32x2 %0, %1, %2, %0;" : "+l"(c) : "l"(a), "l"(b));
}

// ---------------- degree / count ----------------
__global__ void k_init(float* deg, int* cnt, int n) {
    int i = blockIdx.x * blockDim.x + threadIdx.x;
    if (i < n) { deg[i] = 1.0f; cnt[i] = 0; }   // self-loop weight 1
}

__global__ void k_deg_cnt(const int* __restrict__ ei, const float* __restrict__ ew,
                          float* deg, int* cnt, int e) {
    int i = blockIdx.x * blockDim.x + threadIdx.x;
    if (i < e) {
        int d = ei[e + i];
        atomicAdd(&deg[d], ew[i]);
        atomicAdd(&cnt[d], 1);
    }
}

__global__ void k_rsqrt(float* deg, int n) {
    int i = blockIdx.x * blockDim.x + threadIdx.x;
    if (i < n) { float d = deg[i]; deg[i] = (d > 0.0f) ? rsqrtf(d) : 0.0f; }
}

// ---------------- multi-block exclusive scan: cnt -> off, cursor ----------------
__device__ __forceinline__ int warp_incl_scan(int v, int lane) {
#pragma unroll
    for (int o = 1; o < 32; o <<= 1) {
        int t = __shfl_up_sync(0xFFFFFFFFu, v, o);
        if (lane >= o) v += t;
    }
    return v;
}

__device__ __forceinline__ int block_incl_scan(int v, int tid) {
    __shared__ int ws[8];
    const int lane = tid & 31, w = tid >> 5;
    int s = warp_incl_scan(v, lane);
    if (lane == 31) ws[w] = s;
    __syncthreads();
    if (w == 0) {
        int t = (lane < 8) ? ws[lane] : 0;
        t = warp_incl_scan(t, lane);
        if (lane < 8) ws[lane] = t;
    }
    __syncthreads();
    return s + ((w > 0) ? ws[w - 1] : 0);
}

__global__ void k_scan_part(const int* __restrict__ cnt, int* __restrict__ part, int n) {
    __shared__ int ws[8];
    int i = blockIdx.x * 256 + threadIdx.x;
    int v = (i < n) ? cnt[i] : 0;
    const int lane = threadIdx.x & 31, w = threadIdx.x >> 5;
#pragma unroll
    for (int o = 16; o > 0; o >>= 1) v += __shfl_xor_sync(0xFFFFFFFFu, v, o);
    if (lane == 0) ws[w] = v;
    __syncthreads();
    if (threadIdx.x == 0) {
        int s = 0;
#pragma unroll
        for (int j = 0; j < 8; j++) s += ws[j];
        part[blockIdx.x] = s;
    }
}

__global__ void k_scan_mid(int* __restrict__ part, int nb) {
    int t = threadIdx.x;
    int v = (t < nb) ? part[t] : 0;
    int incl = block_incl_scan(v, t);
    if (t < nb) part[t] = incl - v;     // exclusive
}

__global__ void k_scan_fin(const int* __restrict__ cnt, const int* __restrict__ part,
                           int* __restrict__ off, int* __restrict__ cursor, int n) {
    int i = blockIdx.x * 256 + threadIdx.x;
    int v = (i < n) ? cnt[i] : 0;
    int incl = block_incl_scan(v, threadIdx.x);
    int excl = part[blockIdx.x] + incl - v;
    if (i < n) { off[i] = excl; cursor[i] = excl; }
    if (i == n - 1) off[n] = excl + v;
}

// ---------------- CSR placement + norm precompute ----------------
__global__ void k_place(const int* __restrict__ ei, const float* __restrict__ ew,
                        const float* __restrict__ dis,
                        int* __restrict__ cursor,
                        int* __restrict__ csrc, float* __restrict__ cnrm, int e) {
    int i = blockIdx.x * blockDim.x + threadIdx.x;
    if (i >= e) return;
    int s = ei[i];
    int d = ei[e + i];
    float nrm = dis[s] * ew[i] * dis[d];
    int pos = atomicAdd(&cursor[d], 1);
    csrc[pos] = s;
    cnrm[pos] = nrm;
}

// ---------------- SGEMM (FFMA2, fragment double-buffer) — R13 proven version ----------------
// BM=128, BN=128, BK=16, 256 threads, 8x8/thread, 2-stage smem pipeline.
__device__ __forceinline__ void tile_mac(const float (*__restrict__ As)[128],
                                         const float (*__restrict__ Bs)[128],
                                         unsigned long long acc2[8][4],
                                         int ty, int tx) {
    float4 fa0 = *(const float4*)&As[0][ty * 8];
    float4 fa1 = *(const float4*)&As[0][ty * 8 + 4];
    ulonglong2 fb0 = *(const ulonglong2*)&Bs[0][tx * 8];
    ulonglong2 fb1 = *(const ulonglong2*)&Bs[0][tx * 8 + 4];
#pragma unroll
    for (int kk = 0; kk < 16; kk++) {
        float4 na0, na1; ulonglong2 nb0, nb1;
        if (kk < 15) {
            na0 = *(const float4*)&As[kk + 1][ty * 8];
            na1 = *(const float4*)&As[kk + 1][ty * 8 + 4];
            nb0 = *(const ulonglong2*)&Bs[kk + 1][tx * 8];
            nb1 = *(const ulonglong2*)&Bs[kk + 1][tx * 8 + 4];
        }
        unsigned long long b2[4] = {fb0.x, fb0.y, fb1.x, fb1.y};
        unsigned long long a2[8] = {
            pack2(fa0.x), pack2(fa0.y), pack2(fa0.z), pack2(fa0.w),
            pack2(fa1.x), pack2(fa1.y), pack2(fa1.z), pack2(fa1.w)};
#pragma unroll
        for (int i = 0; i < 8; i++)
#pragma unroll
            for (int j = 0; j < 4; j++)
                ffma2(acc2[i][j], a2[i], b2[j]);
        fa0 = na0; fa1 = na1; fb0 = nb0; fb1 = nb1;
    }
}

__global__ __launch_bounds__(256, 2)
void k_sgemm(const float* __restrict__ A, const float* __restrict__ B,
             float* __restrict__ C, int M, int N, int K) {
    __shared__ float As[2][16][128];
    __shared__ float Bs[2][16][128];

    const int tid = threadIdx.x;
    const int tx  = tid & 15;
    const int ty  = tid >> 4;
    const int blockRow = blockIdx.y;
    const int blockCol = blockIdx.x;

    const int aRow = tid >> 2;
    const int aCol = (tid & 3) * 4;
    const int bRow = tid >> 5;
    const int bCol = (tid & 31) * 4;

    const float* Ablk = A + (size_t)blockRow * 128 * K;
    const float* Bblk = B + blockCol * 128;

    unsigned long long acc2[8][4];
#pragma unroll
    for (int i = 0; i < 8; i++)
#pragma unroll
        for (int j = 0; j < 4; j++) acc2[i][j] = 0ull;

    float4 ra[2];

#pragma unroll
    for (int r = 0; r < 2; r++) {
        int row  = aRow + r * 64;
        int grow = blockRow * 128 + row;
        ra[r] = make_float4(0.f, 0.f, 0.f, 0.f);
        if (grow < M)
            ra[r] = *(const float4*)(Ablk + (size_t)row * K + aCol);
    }
#pragma unroll
    for (int r = 0; r < 2; r++) {
        int row = bRow + r * 8;
        cp_async16(smem_u32(&Bs[0][row][bCol]), Bblk + (size_t)row * N + bCol);
    }
    CP_COMMIT();
#pragma unroll
    for (int r = 0; r < 2; r++) {
        int row = aRow + r * 64;
        As[0][aCol + 0][row] = ra[r].x;
        As[0][aCol + 1][row] = ra[r].y;
        As[0][aCol + 2][row] = ra[r].z;
        As[0][aCol + 3][row] = ra[r].w;
    }
    CP_WAIT0();
    __syncthreads();

    int buf = 0;
    for (int k0 = 16; k0 < K; k0 += 16) {
        int nbuf = buf ^ 1;
#pragma unroll
        for (int r = 0; r < 2; r++) {
            int row = bRow + r * 8;
            cp_async16(smem_u32(&Bs[nbuf][row][bCol]),
                       Bblk + (size_t)(k0 + row) * N + bCol);
        }
        CP_COMMIT();
#pragma unroll
        for (int r = 0; r < 2; r++) {
            int row  = aRow + r * 64;
            int grow = blockRow * 128 + row;
            ra[r] = make_float4(0.f, 0.f, 0.f, 0.f);
            if (grow < M)
                ra[r] = *(const float4*)(Ablk + (size_t)row * K + k0 + aCol);
        }

        tile_mac(As[buf], Bs[buf], acc2, ty, tx);

#pragma unroll
        for (int r = 0; r < 2; r++) {
            int row = aRow + r * 64;
            As[nbuf][aCol + 0][row] = ra[r].x;
            As[nbuf][aCol + 1][row] = ra[r].y;
            As[nbuf][aCol + 2][row] = ra[r].z;
            As[nbuf][aCol + 3][row] = ra[r].w;
        }
        CP_WAIT0();
        __syncthreads();
        buf = nbuf;
    }

    tile_mac(As[buf], Bs[buf], acc2, ty, tx);

    int colBase = blockCol * 128 + tx * 8;
#pragma unroll
    for (int i = 0; i < 8; i++) {
        int grow = blockRow * 128 + ty * 8 + i;
        if (grow >= M) continue;
        size_t off = (size_t)grow * N + colBase;
        float4 c0, c1;
        unpack2(acc2[i][0], c0.x, c0.y);
        unpack2(acc2[i][1], c0.z, c0.w);
        unpack2(acc2[i][2], c1.x, c1.y);
        unpack2(acc2[i][3], c1.z, c1.w);
        *(float4*)(C + off)     = c0;
        *(float4*)(C + off + 4) = c1;
    }
}

// ---------------- fused CSR aggregation + BN/ReLU or L2norm (4-wide edge unroll) ----------------
template <int F, bool FINAL>
__global__ __launch_bounds__(256)
void k_agg(const float* __restrict__ t,
           const int* __restrict__ off, const int* __restrict__ csrc,
           const float* __restrict__ cnrm,
           const float* __restrict__ bias, const float* __restrict__ dis,
           const float* __restrict__ bg, const float* __restrict__ bb,
           const float* __restrict__ bm, const float* __restrict__ bv,
           float* __restrict__ out, int n) {
    const int row = blockIdx.x * 8 + (threadIdx.x >> 5);
    if (row >= n) return;
    const int lane = threadIdx.x & 31;
    constexpr int V = F / 128;

    float4 acc[V];
    {
        const float dvv = dis[row];
        const float d2 = dvv * dvv;
        const float4* trow = (const float4*)(t + (size_t)row * F);
#pragma unroll
        for (int j = 0; j < V; j++) {
            float4 tv = trow[lane + j * 32];
            float4 bvv = ((const float4*)bias)[lane + j * 32];
            acc[j].x = bvv.x + tv.x * d2;
            acc[j].y = bvv.y + tv.y * d2;
            acc[j].z = bvv.z + tv.z * d2;
            acc[j].w = bvv.w + tv.w * d2;
        }
    }

    int e = __ldg(&off[row]);
    const int e1 = __ldg(&off[row + 1]);

    // 4-wide unroll: 4 independent gather streams to raise MLP
    for (; e + 3 < e1; e += 4) {
        int s0 = __ldg(&csrc[e]);
        int s1 = __ldg(&csrc[e + 1]);
        int s2 = __ldg(&csrc[e + 2]);
        int s3 = __ldg(&csrc[e + 3]);
        float w0 = __ldg(&cnrm[e]);
        float w1 = __ldg(&cnrm[e + 1]);
        float w2 = __ldg(&cnrm[e + 2]);
        float w3 = __ldg(&cnrm[e + 3]);
        const float4* r0 = (const float4*)(t + (size_t)s0 * F);
        const float4* r1 = (const float4*)(t + (size_t)s1 * F);
        const float4* r2 = (const float4*)(t + (size_t)s2 * F);
        const float4* r3 = (const float4*)(t + (size_t)s3 * F);
#pragma unroll
        for (int j = 0; j < V; j++) {
            float4 x0 = r0[lane + j * 32];
            float4 x1 = r1[lane + j * 32];
            float4 x2 = r2[lane + j * 32];
            float4 x3 = r3[lane + j * 32];
            acc[j].x += w0 * x0.x + w1 * x1.x + w2 * x2.x + w3 * x3.x;
            acc[j].y += w0 * x0.y + w1 * x1.y + w2 * x2.y + w3 * x3.y;
            acc[j].z += w0 * x0.z + w1 * x1.z + w2 * x2.z + w3 * x3.z;
            acc[j].w += w0 * x0.w + w1 * x1.w + w2 * x2.w + w3 * x3.w;
        }
    }
    for (; e < e1; e++) {
        int s0 = __ldg(&csrc[e]);
        float w0 = __ldg(&cnrm[e]);
        const float4* r0 = (const float4*)(t + (size_t)s0 * F);
#pragma unroll
        for (int j = 0; j < V; j++) {
            float4 x0 = r0[lane + j * 32];
            acc[j].x += w0 * x0.x;
            acc[j].y += w0 * x0.y;
            acc[j].z += w0 * x0.z;
            acc[j].w += w0 * x0.w;
        }
    }

    if (FINAL) {
        float ss = acc[0].x * acc[0].x + acc[0].y * acc[0].y
                 + acc[0].z * acc[0].z + acc[0].w * acc[0].w;
#pragma unroll
        for (int o = 16; o > 0; o >>= 1)
            ss += __shfl_xor_sync(0xFFFFFFFFu, ss, o);
        float inv = 1.0f / fmaxf(sqrtf(ss), NORM_EPS);
        float4 o4 = make_float4(acc[0].x * inv, acc[0].y * inv,
                                acc[0].z * inv, acc[0].w * inv);
        ((float4*)(out + (size_t)row * F))[lane] = o4;
    } else {
        float4* orow = (float4*)(out + (size_t)row * F);
#pragma unroll
        for (int j = 0; j < V; j++) {
            int c = lane + j * 32;
            float4 g = ((const float4*)bg)[c];
            float4 b = ((const float4*)bb)[c];
            float4 m = ((const float4*)bm)[c];
            float4 v = ((const float4*)bv)[c];
            float4 o;
            o.x = fmaxf((acc[j].x - m.x) * rsqrtf(v.x + BN_EPS) * g.x + b.x, 0.0f);
            o.y = fmaxf((acc[j].y - m.y) * rsqrtf(v.y + BN_EPS) * g.y + b.y, 0.0f);
            o.z = fmaxf((acc[j].z - m.z) * rsqrtf(v.z + BN_EPS) * g.z + b.z, 0.0f);
            o.w = fmaxf((acc[j].w - m.w) * rsqrtf(v.w + BN_EPS) * g.w + b.w, 0.0f);
            orow[c] = o;
        }
    }
}

// ---------------- launch ----------------
extern "C" void kernel_launch(void* const* d_in, const int* in_sizes, int n_in,
                              void* d_out, int out_size) {
    const float* x   = (const float*)d_in[0];
    const int*   ei  = (const int*)d_in[1];     // int32 (JAX x64 disabled)
    const float* ew  = (const float*)d_in[2];
    const float* W1  = (const float*)d_in[3];
    const float* b1  = (const float*)d_in[4];
    const float* W2  = (const float*)d_in[5];
    const float* b2  = (const float*)d_in[6];
    const float* W3  = (const float*)d_in[7];
    const float* b3  = (const float*)d_in[8];
    const float* bn1_g = (const float*)d_in[9];
    const float* bn1_b = (const float*)d_in[10];
    const float* bn1_m = (const float*)d_in[11];
    const float* bn1_v = (const float*)d_in[12];
    const float* bn2_g = (const float*)d_in[13];
    const float* bn2_b = (const float*)d_in[14];
    const float* bn2_m = (const float*)d_in[15];
    const float* bn2_v = (const float*)d_in[16];
    float* out = (float*)d_out;

    const int n = NN;
    const int e = in_sizes[2];   // 800000

    float *deg, *t, *h, *cnrm;
    int *cnt, *off, *cursor, *csrc, *part;
    cudaGetSymbolAddress((void**)&deg, g_deg);
    cudaGetSymbolAddress((void**)&t,   g_t);
    cudaGetSymbolAddress((void**)&h,   g_h);
    cudaGetSymbolAddress((void**)&cnt, g_cnt);
    cudaGetSymbolAddress((void**)&off, g_off);
    cudaGetSymbolAddress((void**)&cursor, g_cursor);
    cudaGetSymbolAddress((void**)&csrc, g_csr_src);
    cudaGetSymbolAddress((void**)&cnrm, g_csr_nrm);
    cudaGetSymbolAddress((void**)&part, g_part);

    static cudaStream_t s_pre = nullptr;
    static cudaEvent_t ev_fork = nullptr, ev_join = nullptr;
    if (!s_pre) {
        cudaStreamCreateWithFlags(&s_pre, cudaStreamNonBlocking);
        cudaEventCreateWithFlags(&ev_fork, cudaEventDisableTiming);
        cudaEventCreateWithFlags(&ev_join, cudaEventDisableTiming);
    }

    const int TB = 256;
    const int nb = NBLK;
    const int mBlocks = (n + 127) / 128;
    const int aBlocks = (n + 7) / 8;

    // ---- fork: graph preprocessing on side stream, layer-1 GEMM on main ----
    cudaEventRecord(ev_fork, 0);
    cudaStreamWaitEvent(s_pre, ev_fork, 0);
    k_init<<<(n + TB - 1) / TB, TB, 0, s_pre>>>(deg, cnt, n);
    k_deg_cnt<<<(e + TB - 1) / TB, TB, 0, s_pre>>>(ei, ew, deg, cnt, e);
    k_rsqrt<<<(n + TB - 1) / TB, TB, 0, s_pre>>>(deg, n);
    k_scan_part<<<nb, 256, 0, s_pre>>>(cnt, part, n);
    k_scan_mid<<<1, 256, 0, s_pre>>>(part, nb);
    k_scan_fin<<<nb, 256, 0, s_pre>>>(cnt, part, off, cursor, n);
    k_place<<<(e + TB - 1) / TB, TB, 0, s_pre>>>(ei, ew, deg, cursor, csrc, cnrm, e);
    cudaEventRecord(ev_join, s_pre);

    // ---- layer 1 ----
    k_sgemm<<<dim3(HID / 128, mBlocks), 256>>>(x, W1, t, n, HID, IN_DIM);
    cudaStreamWaitEvent(0, ev_join, 0);   // join before aggregation
    k_agg<HID, false><<<aBlocks, 256>>>(t, off, csrc, cnrm, b1, deg,
                                        bn1_g, bn1_b, bn1_m, bn1_v, h, n);
    // ---- layer 2 ----
    k_sgemm<<<dim3(HID / 128, mBlocks), 256>>>(h, W2, t, n, HID, HID);
    k_agg<HID, false><<<aBlocks, 256>>>(t, off, csrc, cnrm, b2, deg,
                                        bn2_g, bn2_b, bn2_m, bn2_v, h, n);
    // ---- layer 3 ----
    k_sgemm<<<dim3(OUT_DIM / 128, mBlocks), 256>>>(h, W3, t, n, OUT_DIM, HID);
    k_agg<OUT_DIM, true><<<aBlocks, 256>>>(t, off, csrc, cnrm, b3, deg,
                                           nullptr, nullptr, nullptr, nullptr, out, n);
}